// round 15
// baseline (speedup 1.0000x reference)
#include <cuda_runtime.h>
#include <cuda_fp16.h>
#include <math.h>
#include <stdint.h>

#define Bsz 4
#define NG  8192
#define Cdim 256
#define Hh  128
#define Ww  128
#define NT  512
#define EPSLN 1e-5f
#define ATTN_SCALE 0.17677669529663687f

__device__ __half g_S  [(size_t)Bsz*NG*Cdim];     // sampled S (fp16, 1x path)
__device__ __half g_vt [(size_t)Bsz*Hh*Ww*Cdim];  // value transposed (B,H,W,C), fp16
__device__ float  g_oa [Bsz*NG*96];
__device__ float  g_wc [96*Cdim];
__device__ float  g_bc [96];
// rank-3 attention precomputes (gamma dropped: cancels in softmax ratio)
__device__ float  g_kv6[6*256];                   // Kx Ky K1 Vx Vy V1
__device__ float  g_A  [16*256];                  // coef weights (e = m*2+{x,y})
__device__ float  g_Ab [16];
__device__ float  g_Mw [16*256];                  // ctx->mha weights (e = m*2+{x,y})
__device__ float  g_Mc [256];                     // const vector (V1 path + mha_b)
__device__ float  g_coef[(size_t)Bsz*NG*16];
__device__ float  g_R  [(size_t)Bsz*NG*16];

// ---- weight concat (offs|attw) ----
__global__ __launch_bounds__(256) void k_prep(const float* __restrict__ ow,
                                              const float* __restrict__ ob,
                                              const float* __restrict__ aw,
                                              const float* __restrict__ ab) {
    int i = blockIdx.x * 256 + threadIdx.x;
    if (i < 64 * 256)                 g_wc[i] = ow[i];
    else if (i < 96 * 256)            g_wc[i] = aw[i - 64 * 256];
    else if (i < 96 * 256 + 64)       g_bc[i - 96 * 256] = ob[i - 96 * 256];
    else if (i < 96 * 256 + 96)       g_bc[i - 96 * 256] = ab[i - 96 * 256 - 64];
}

// ---- rank-3 K/V basis: 6 blocks, one per output vector ----
__global__ __launch_bounds__(256) void k_precomp(const float* __restrict__ in_w,
                                                 const float* __restrict__ in_b,
                                                 const float* __restrict__ tw,
                                                 const float* __restrict__ tb) {
    __shared__ float stw[256];
    int bi = blockIdx.x;            // 0..5 : Kx Ky K1 Vx Vy V1
    int c = threadIdx.x;
    int comp = bi % 3;
    int wrow = (bi < 3) ? (256 + c) : (512 + c);
    stw[c] = (comp == 0) ? tw[c * 2] : (comp == 1) ? tw[c * 2 + 1] : tb[c];
    __syncthreads();
    const float4* wp = (const float4*)(in_w + (size_t)wrow * 256);
    float acc = 0.f;
#pragma unroll 8
    for (int j = 0; j < 64; j++) {
        float4 v = wp[j];
        acc = fmaf(v.x, stw[j * 4],     acc);
        acc = fmaf(v.y, stw[j * 4 + 1], acc);
        acc = fmaf(v.z, stw[j * 4 + 2], acc);
        acc = fmaf(v.w, stw[j * 4 + 3], acc);
    }
    if (bi == 2) acc += in_b[256 + c];
    if (bi == 5) acc += in_b[512 + c];
    g_kv6[bi * 256 + c] = acc;
}

// ---- fold q-proj into coef weights A (x,y only), mha-out into Mw/Mc ----
__global__ __launch_bounds__(256) void k_precomp2(const float* __restrict__ in_w,
                                                  const float* __restrict__ in_b,
                                                  const float* __restrict__ mw,
                                                  const float* __restrict__ mb) {
    int bi = blockIdx.x, t = threadIdx.x;
    if (bi < 16) {                       // A[e][j] = sum_c wq[m*32+c][j] * KC[comp][m*32+c]
        int m = bi >> 1, comp = bi & 1;
        const float* KC = g_kv6 + comp * 256 + m * 32;
        float a = 0.f;
#pragma unroll 8
        for (int c = 0; c < 32; c++)
            a = fmaf(in_w[(size_t)(m * 32 + c) * 256 + t], KC[c], a);
        g_A[bi * 256 + t] = a * ATTN_SCALE;
        if (t < 32) {
            float v = in_b[m * 32 + t] * KC[t];
#pragma unroll
            for (int o = 16; o; o >>= 1) v += __shfl_xor_sync(0xffffffffu, v, o);
            if (t == 0) g_Ab[bi] = v * ATTN_SCALE;
        }
    } else if (bi < 32) {                // Mw[e2][o] = sum_c mha_w[o][m*32+c] * VC[comp][..]
        int e2 = bi - 16, m = e2 >> 1, comp = e2 & 1;
        const float* VC = g_kv6 + (3 + comp) * 256 + m * 32;
        const float* mwr = mw + (size_t)t * 256 + m * 32;
        float a = 0.f;
#pragma unroll 8
        for (int c = 0; c < 32; c++) a = fmaf(mwr[c], VC[c], a);
        g_Mw[e2 * 256 + t] = a;
    } else {                             // Mc[o] = sum_c mha_w[o][c]*V1[c] + mha_b[o]
        const float* V1 = g_kv6 + 5 * 256;
        const float* mwr = mw + (size_t)t * 256;
        float a = mb[t];
        for (int c = 0; c < 256; c++) a = fmaf(mwr[c], V1[c], a);
        g_Mc[t] = a;
    }
}

// ---- thin coef GEMM v4: k-outer broadcast, 4 thr/row, 64 rows/block, grid 512 ----
__global__ __launch_bounds__(256) void k_coef(const float* __restrict__ q) {
    __shared__ float sA[256][16];   // sA[k][e]
    __shared__ float sAb[16];
    int tid = threadIdx.x;
    for (int i = tid; i < 4096; i += 256) sA[i & 255][i >> 8] = g_A[i];
    if (tid < 16) sAb[tid] = g_Ab[tid];
    __syncthreads();

    int row = blockIdx.x * 64 + (tid >> 2);
    int qt = tid & 3;               // k-quarter: [qt*64, qt*64+64)
    const float4* qp = (const float4*)(q + (size_t)row * 256 + qt * 64);
    float acc[16];
#pragma unroll
    for (int e = 0; e < 16; e++) acc[e] = 0.f;

#pragma unroll
    for (int i = 0; i < 16; i += 4) {
        float4 v[4];
#pragma unroll
        for (int j = 0; j < 4; j++) v[j] = qp[i + j];
#pragma unroll
        for (int j = 0; j < 4; j++) {
            int kb = qt * 64 + (i + j) * 4;
            const float* vv = (const float*)&v[j];
#pragma unroll
            for (int s = 0; s < 4; s++) {
                float val = vv[s];
                const float4* ap = (const float4*)sA[kb + s];
                float4 a0 = ap[0], a1 = ap[1], a2 = ap[2], a3 = ap[3];
                acc[0]  = fmaf(val, a0.x, acc[0]);  acc[1]  = fmaf(val, a0.y, acc[1]);
                acc[2]  = fmaf(val, a0.z, acc[2]);  acc[3]  = fmaf(val, a0.w, acc[3]);
                acc[4]  = fmaf(val, a1.x, acc[4]);  acc[5]  = fmaf(val, a1.y, acc[5]);
                acc[6]  = fmaf(val, a1.z, acc[6]);  acc[7]  = fmaf(val, a1.w, acc[7]);
                acc[8]  = fmaf(val, a2.x, acc[8]);  acc[9]  = fmaf(val, a2.y, acc[9]);
                acc[10] = fmaf(val, a2.z, acc[10]); acc[11] = fmaf(val, a2.w, acc[11]);
                acc[12] = fmaf(val, a3.x, acc[12]); acc[13] = fmaf(val, a3.y, acc[13]);
                acc[14] = fmaf(val, a3.z, acc[14]); acc[15] = fmaf(val, a3.w, acc[15]);
            }
        }
    }
    // combine the four k-quarters (lanes qt = 0..3 of each group)
#pragma unroll
    for (int e = 0; e < 16; e++) {
        acc[e] += __shfl_xor_sync(0xffffffffu, acc[e], 1);
        acc[e] += __shfl_xor_sync(0xffffffffu, acc[e], 2);
    }
    int e0 = qt * 4;
    float4 o;
    o.x = acc[e0]     + sAb[e0];     o.y = acc[e0 + 1] + sAb[e0 + 1];
    o.z = acc[e0 + 2] + sAb[e0 + 2]; o.w = acc[e0 + 3] + sAb[e0 + 3];
    *(float4*)(g_coef + (size_t)row * 16 + e0) = o;
}

// ---- rank-3 attention: thread = (query, head); gamma-free scores ----
__global__ __launch_bounds__(256) void k_attn3(const float* __restrict__ tp) {
    __shared__ float sxy[NT * 2];
    int bi = blockIdx.x;                  // 1024 = B * 256
    int b = bi >> 8, qt = bi & 255;
    int tid = threadIdx.x;
    for (int t = tid; t < NT; t += 256) {
        float2 v = ((const float2*)tp)[b * NT + t];
        sxy[t * 2] = v.x; sxy[t * 2 + 1] = v.y;
    }
    __syncthreads();

    int m = tid & 7;
    int g = qt * 32 + (tid >> 3);
    size_t gi = (size_t)b * NG + g;
    const float* cf = g_coef + gi * 16 + m * 2;
    float al = cf[0], be = cf[1];
    float Sp = 0.f, Sx = 0.f, Sy = 0.f;
#pragma unroll 4
    for (int t = 0; t < NT; t++) {
        float2 xy = ((const float2*)sxy)[t];
        float s = fmaf(al, xy.x, be * xy.y);
        float p = __expf(s);
        Sp += p;
        Sx = fmaf(p, xy.x, Sx);
        Sy = fmaf(p, xy.y, Sy);
    }
    float inv = 1.f / Sp;
    float2 r = {Sx * inv, Sy * inv};
    ((float2*)(g_R + gi * 16))[m] = r;
}

// ---- FUSED: mha-out(K=16) + residual + LN (smem) + offs/attw GEMM (N=96) ----
// 64 rows/block, grid 512. smem: Xs[64][260] | sMw[16][256] | sMc[256] | sR[64][16]
//                               | Bs[16][100] | red[64]
#define XS_STRIDE 260
#define SM_XS    0
#define SM_MW    (64 * XS_STRIDE)            // 16640
#define SM_MC    (SM_MW + 4096)              // 20736
#define SM_R     (SM_MC + 256)               // 20992
#define SM_BS    (SM_R + 1024)               // 22016
#define SM_RED   (SM_BS + 1600)              // 23616
#define SM_CTXOFFS_BYTES ((23616 + 64) * 4)  // 94720

__global__ __launch_bounds__(256) void k_ctxoffs(const float* __restrict__ q_in,
                                                 const float* __restrict__ lng,
                                                 const float* __restrict__ lnb) {
    extern __shared__ float sm[];
    float* Xs  = sm + SM_XS;
    float* sMw = sm + SM_MW;
    float* sMc = sm + SM_MC;
    float* sR  = sm + SM_R;
    float* Bs  = sm + SM_BS;
    float* red = sm + SM_RED;      // red[w*8 + r]
    int tid = threadIdx.x;
    int row0 = blockIdx.x * 64;

    for (int i = tid; i < 4096; i += 256) sMw[i] = g_Mw[i];
    sMc[tid] = g_Mc[tid];
    for (int i = tid; i < 1024; i += 256) sR[i] = g_R[(size_t)row0 * 16 + i];
    __syncthreads();

    int lane = tid & 31, w = tid >> 5;
    float gg = lng[tid], bbn = lnb[tid];

    // ---- phase 1: 8 iterations of 8 rows -> LN rows into Xs ----
    for (int rr = 0; rr < 8; rr++) {
        float xv[8];
#pragma unroll
        for (int r = 0; r < 8; r++) {
            const float* Rr = sR + (rr * 8 + r) * 16;
            float acc = sMc[tid];
#pragma unroll
            for (int k = 0; k < 16; k++) acc = fmaf(Rr[k], sMw[k * 256 + tid], acc);
            xv[r] = acc + q_in[(size_t)(row0 + rr * 8 + r) * 256 + tid];
        }
#pragma unroll
        for (int r = 0; r < 8; r++) {
            float s = xv[r];
#pragma unroll
            for (int o = 16; o; o >>= 1) s += __shfl_xor_sync(0xffffffffu, s, o);
            if (!lane) red[w * 8 + r] = s;
        }
        __syncthreads();
        float mu[8];
#pragma unroll
        for (int r = 0; r < 8; r++) {
            float tot = 0.f;
#pragma unroll
            for (int i = 0; i < 8; i++) tot += red[i * 8 + r];
            mu[r] = tot * (1.f / 256.f);
        }
        __syncthreads();
#pragma unroll
        for (int r = 0; r < 8; r++) {
            float d = xv[r] - mu[r];
            float s = d * d;
#pragma unroll
            for (int o = 16; o; o >>= 1) s += __shfl_xor_sync(0xffffffffu, s, o);
            if (!lane) red[w * 8 + r] = s;
        }
        __syncthreads();
#pragma unroll
        for (int r = 0; r < 8; r++) {
            float tot = 0.f;
#pragma unroll
            for (int i = 0; i < 8; i++) tot += red[i * 8 + r];
            float inv = rsqrtf(tot * (1.f / 256.f) + EPSLN);
            Xs[(rr * 8 + r) * XS_STRIDE + tid] = (xv[r] - mu[r]) * inv * gg + bbn;
        }
        __syncthreads();
    }

    // ---- phase 2: GEMM 64x96 = Xs[64x256] @ wc[96x256]^T ----
    int rg = tid >> 4;              // 16 groups of 4 rows
    int cg = tid & 15;              // 16 groups of 6 cols
    float acc[4][6];
#pragma unroll
    for (int i = 0; i < 4; i++)
#pragma unroll
        for (int j = 0; j < 6; j++) acc[i][j] = 0.f;

    for (int kt = 0; kt < 16; kt++) {
        for (int i = tid; i < 1536; i += 256) {
            int n = i >> 4, kk = i & 15;
            Bs[kk * 100 + n] = g_wc[(size_t)n * 256 + kt * 16 + kk];
        }
        __syncthreads();
#pragma unroll
        for (int kk = 0; kk < 16; kk++) {
            int k = kt * 16 + kk;
            float a0 = Xs[(rg * 4 + 0) * XS_STRIDE + k];
            float a1 = Xs[(rg * 4 + 1) * XS_STRIDE + k];
            float a2 = Xs[(rg * 4 + 2) * XS_STRIDE + k];
            float a3 = Xs[(rg * 4 + 3) * XS_STRIDE + k];
            const float* bp = Bs + kk * 100 + cg * 6;
            float2 b01 = *(const float2*)bp;
            float2 b23 = *(const float2*)(bp + 2);
            float2 b45 = *(const float2*)(bp + 4);
            float bb[6] = {b01.x, b01.y, b23.x, b23.y, b45.x, b45.y};
            float aa[4] = {a0, a1, a2, a3};
#pragma unroll
            for (int i = 0; i < 4; i++)
#pragma unroll
                for (int j = 0; j < 6; j++) acc[i][j] = fmaf(aa[i], bb[j], acc[i][j]);
        }
        __syncthreads();
    }
    int c0 = cg * 6;
    float b0 = g_bc[c0],     b1 = g_bc[c0 + 1], b2 = g_bc[c0 + 2];
    float b3 = g_bc[c0 + 3], b4 = g_bc[c0 + 4], b5 = g_bc[c0 + 5];
#pragma unroll
    for (int i = 0; i < 4; i++) {
        float* dst = g_oa + (size_t)(row0 + rg * 4 + i) * 96 + c0;
        float2 o0 = {acc[i][0] + b0, acc[i][1] + b1};
        float2 o1 = {acc[i][2] + b2, acc[i][3] + b3};
        float2 o2 = {acc[i][4] + b4, acc[i][5] + b5};
        *(float2*)dst = o0; *(float2*)(dst + 2) = o1; *(float2*)(dst + 4) = o2;
    }
}

// ---- fp16 HMMA final projection: Y[32768x256] = S(half) @ W^T + bias ----
__global__ __launch_bounds__(256) void gemm_hmma(const __half* __restrict__ X,
                                                 const float* __restrict__ W,
                                                 const float* __restrict__ bias,
                                                 float* __restrict__ Y) {
    __shared__ __half Ah[128][40];
    __shared__ __half Bh[64][40];
    int tid = threadIdx.x;
    int row0 = blockIdx.y * 128, n0b = blockIdx.x * 64;
    int w = tid >> 5, lane = tid & 31, grp = lane >> 2, qid = lane & 3;
    float acc[8][4];
#pragma unroll
    for (int j = 0; j < 8; j++)
#pragma unroll
        for (int i = 0; i < 4; i++) acc[j][i] = 0.f;

    int ar = tid >> 1, aseg = (tid & 1) * 16;
    int br = tid >> 2, bq = (tid & 3) * 8;
    const __half* Xp = X + (size_t)(row0 + ar) * 256 + aseg;
    const float* Wp = W + (size_t)(n0b + br) * 256 + bq;

    for (int kt = 0; kt < 8; kt++) {
        int k0t = kt * 32;
        {
            uint4 v0 = *(const uint4*)(Xp + k0t);
            uint4 v1 = *(const uint4*)(Xp + k0t + 8);
            *(uint4*)&Ah[ar][aseg] = v0;
            *(uint4*)&Ah[ar][aseg + 8] = v1;
        }
        {
            float4 v0 = *(const float4*)(Wp + k0t);
            float4 v1 = *(const float4*)(Wp + k0t + 4);
            __half2 h[4];
            h[0] = __floats2half2_rn(v0.x, v0.y); h[1] = __floats2half2_rn(v0.z, v0.w);
            h[2] = __floats2half2_rn(v1.x, v1.y); h[3] = __floats2half2_rn(v1.z, v1.w);
            *(uint4*)&Bh[br][bq] = *(uint4*)h;
        }
        __syncthreads();
#pragma unroll
        for (int ks = 0; ks < 2; ks++) {
            int k0 = ks * 16;
            uint32_t a0 = *(const uint32_t*)&Ah[w * 16 + grp][k0 + qid * 2];
            uint32_t a1 = *(const uint32_t*)&Ah[w * 16 + grp + 8][k0 + qid * 2];
            uint32_t a2 = *(const uint32_t*)&Ah[w * 16 + grp][k0 + qid * 2 + 8];
            uint32_t a3 = *(const uint32_t*)&Ah[w * 16 + grp + 8][k0 + qid * 2 + 8];
#pragma unroll
            for (int j = 0; j < 8; j++) {
                uint32_t b0 = *(const uint32_t*)&Bh[j * 8 + grp][k0 + qid * 2];
                uint32_t b1 = *(const uint32_t*)&Bh[j * 8 + grp][k0 + qid * 2 + 8];
                asm volatile(
                    "mma.sync.aligned.m16n8k16.row.col.f32.f16.f16.f32 "
                    "{%0,%1,%2,%3}, {%4,%5,%6,%7}, {%8,%9}, {%0,%1,%2,%3};"
                    : "+f"(acc[j][0]), "+f"(acc[j][1]), "+f"(acc[j][2]), "+f"(acc[j][3])
                    : "r"(a0), "r"(a1), "r"(a2), "r"(a3), "r"(b0), "r"(b1));
            }
        }
        __syncthreads();
    }
    int r = row0 + w * 16 + grp;
#pragma unroll
    for (int j = 0; j < 8; j++) {
        int c = n0b + j * 8 + qid * 2;
        float2 bb = *(const float2*)(bias + c);
        float2 o0 = {acc[j][0] + bb.x, acc[j][1] + bb.y};
        float2 o1 = {acc[j][2] + bb.x, acc[j][3] + bb.y};
        *(float2*)(Y + (size_t)r * 256 + c) = o0;
        *(float2*)(Y + (size_t)(r + 8) * 256 + c) = o1;
    }
}

// ---- value (B,C,H,W) fp32 -> (B,H,W,C) fp16 ----
__global__ __launch_bounds__(256) void k_transpose(const float* __restrict__ val) {
    __shared__ float tile[32][33];
    int tx = threadIdx.x, ty = threadIdx.y;
    int b = blockIdx.z, y = blockIdx.y;
    int c0 = (blockIdx.x >> 2) * 32, x0 = (blockIdx.x & 3) * 32;
#pragma unroll
    for (int i = 0; i < 4; i++)
        tile[ty + i * 8][tx] = val[(((size_t)(b * Cdim + c0 + ty + i * 8) * Hh + y) * Ww) + x0 + tx];
    __syncthreads();
#pragma unroll
    for (int i = 0; i < 4; i++)
        g_vt[(((size_t)(b * Hh + y) * Ww + x0 + ty + i * 8) * Cdim) + c0 + tx] =
            __float2half(tile[tx][ty + i * 8]);
}

// ---- bilinear corner accumulate (fp16 values, fp32 math) ----
__device__ __forceinline__ void corner(const __half* __restrict__ vb, int x, int y,
                                       int moff, float w, float* acc) {
    if (x < 0 || x >= Ww || y < 0 || y >= Hh) return;
    const uint4* p = (const uint4*)(vb + ((size_t)(y * Ww + x)) * Cdim + moff);
#pragma unroll
    for (int i = 0; i < 4; i++) {
        uint4 u = p[i];
        const __half2* h = (const __half2*)&u;
#pragma unroll
        for (int j = 0; j < 4; j++) {
            float2 f = __half22float2(h[j]);
            acc[i * 8 + j * 2]     = fmaf(w, f.x, acc[i * 8 + j * 2]);
            acc[i * 8 + j * 2 + 1] = fmaf(w, f.y, acc[i * 8 + j * 2 + 1]);
        }
    }
}

// ---- deformable sampling: thread = (query, m); scrambled fp16 store into g_S ----
__global__ __launch_bounds__(128) void k_sample(const float* __restrict__ refp) {
    int bi = blockIdx.x;            // 2048 = B * 8 * 64
    int tid = threadIdx.x;
    int b = bi >> 9;
    int m = (bi >> 6) & 7;
    int gg = (bi & 63) * 128 + tid;
    int gh = gg >> 8, gl = gg & 255;
    size_t qidx = (size_t)b * NG + gg;
    float rx = refp[qidx * 2], ry = refp[qidx * 2 + 1];
    const float* oar = g_oa + qidx * 96;

    float a0 = oar[64 + m * 4], a1 = oar[64 + m * 4 + 1];
    float a2 = oar[64 + m * 4 + 2], a3 = oar[64 + m * 4 + 3];
    float amx = fmaxf(fmaxf(a0, a1), fmaxf(a2, a3));
    float e0 = __expf(a0 - amx), e1 = __expf(a1 - amx);
    float e2 = __expf(a2 - amx), e3 = __expf(a3 - amx);
    float inv = 1.f / (e0 + e1 + e2 + e3);
    float aw[4] = {e0 * inv, e1 * inv, e2 * inv, e3 * inv};

    const __half* vb = g_vt + (size_t)b * Hh * Ww * Cdim;
    float acc[32];
#pragma unroll
    for (int i = 0; i < 32; i++) acc[i] = 0.f;

#pragma unroll
    for (int p = 0; p < 4; p++) {
        float gx = (rx + oar[m * 8 + p * 2]) * (float)Ww - 0.5f;
        float gy = (ry + oar[m * 8 + p * 2 + 1]) * (float)Hh - 0.5f;
        float x0f = floorf(gx), y0f = floorf(gy);
        float fx = gx - x0f, fy = gy - y0f;
        int x0 = (int)x0f, y0 = (int)y0f;
        float w = aw[p];
        corner(vb, x0,     y0,     m * 32, (1.f - fx) * (1.f - fy) * w, acc);
        corner(vb, x0 + 1, y0,     m * 32, fx * (1.f - fy) * w, acc);
        corner(vb, x0,     y0 + 1, m * 32, (1.f - fx) * fy * w, acc);
        corner(vb, x0 + 1, y0 + 1, m * 32, fx * fy * w, acc);
    }
    // S[b][ch*256 + m*32 + gh][gl]  (fp16)
    __half* S = g_S + (size_t)b * NG * 256 + (size_t)(m * 32 + gh) * 256 + gl;
#pragma unroll
    for (int ch = 0; ch < 32; ch++) S[(size_t)ch * 65536] = __float2half(acc[ch]);
}

extern "C" void kernel_launch(void* const* d_in, const int* in_sizes, int n_in,
                              void* d_out, int out_size) {
    const float* query  = (const float*)d_in[0];
    const float* value  = (const float*)d_in[1];
    const float* refp   = (const float*)d_in[2];
    const float* trajp  = (const float*)d_in[3];
    const float* in_w   = (const float*)d_in[4];
    const float* in_b   = (const float*)d_in[5];
    const float* mha_w  = (const float*)d_in[6];
    const float* mha_b  = (const float*)d_in[7];
    const float* ln_g   = (const float*)d_in[8];
    const float* ln_b   = (const float*)d_in[9];
    const float* traj_w = (const float*)d_in[10];
    const float* traj_b = (const float*)d_in[11];
    const float* offs_w = (const float*)d_in[12];
    const float* offs_b = (const float*)d_in[13];
    const float* attw_w = (const float*)d_in[14];
    const float* attw_b = (const float*)d_in[15];
    const float* out_w  = (const float*)d_in[16];
    const float* out_b  = (const float*)d_in[17];
    float* out = (float*)d_out;

    __half* p_S;
    cudaGetSymbolAddress((void**)&p_S, g_S);

    cudaFuncSetAttribute(k_ctxoffs, cudaFuncAttributeMaxDynamicSharedMemorySize,
                         SM_CTXOFFS_BYTES);

    // (0) weight concat + rank-3 precomputes
    k_prep<<<97, 256>>>(offs_w, offs_b, attw_w, attw_b);
    k_precomp<<<6, 256>>>(in_w, in_b, traj_w, traj_b);
    k_precomp2<<<33, 256>>>(in_w, in_b, mha_w, mha_b);
    // (1) thin coef GEMM v4: coef[g,16] = query @ A^T + Ab
    k_coef<<<512, 256>>>(query);
    // (2) rank-3 attention -> g_R
    k_attn3<<<1024, 256>>>(trajp);
    // (3) FUSED mha-out + residual + LN + offs/attw GEMM -> g_oa
    k_ctxoffs<<<512, 256, SM_CTXOFFS_BYTES>>>(query, ln_g, ln_b);
    // (4) value transpose to fp16 (B,H,W,C)
    k_transpose<<<dim3(32, 128, 4), dim3(32, 8)>>>(value);
    // (5) deformable sampling (fp16 scrambled S)
    k_sample<<<2048, 128>>>(refp);
    // (6) final projection via fp16 HMMA
    gemm_hmma<<<dim3(4, 256), 256>>>(p_S, out_w, out_b, out);
}